// round 1
// baseline (speedup 1.0000x reference)
#include <cuda_runtime.h>
#include <stdint.h>

// Problem constants (shapes fixed by the dataset)
#define NMAX   100000
#define EMAX   1600000
#define IN_C   128
#define HID_C  128
#define OUT_C  64

// ---------------------------------------------------------------------------
// Scratch: __device__ globals (allocation inside kernel_launch is forbidden)
// ---------------------------------------------------------------------------
__device__ float g_xw1 [(size_t)NMAX * HID_C];   // x @ W1                (51.2 MB)
__device__ float g_agg1[(size_t)NMAX * HID_C];   // layer-1 aggregation   (51.2 MB)
__device__ float g_xw2 [(size_t)NMAX * OUT_C];   // h @ W2                (25.6 MB)
__device__ float g_dinv[NMAX];
__device__ int   g_deg [NMAX];
__device__ int   g_is64;                         // edge dtype flag

// ---------------------------------------------------------------------------
// Edge accessor: edge_index may be int64 (jax x64 on) or int32 (x64 off).
// ---------------------------------------------------------------------------
__device__ __forceinline__ int edge_at(const void* ei, int etot, int which, int idx) {
    if (g_is64)
        return (int)((const long long*)ei)[(size_t)which * etot + idx];
    else
        return ((const int*)ei)[(size_t)which * etot + idx];
}

// Detect dtype: for int64 little-endian nonneg values < 2^31, every odd
// int32 word is zero. Random int32 indices in [0,1e5) make a false positive
// astronomically unlikely (16 consecutive zero words).
__global__ void k_detect(const int* ei32) {
    int ok64 = 1;
#pragma unroll
    for (int i = 0; i < 16; i++)
        if (ei32[2 * i + 1] != 0) ok64 = 0;
    g_is64 = ok64;
}

// ---------------------------------------------------------------------------
// Degree / normalization (self-loop => deg starts at 1)
// ---------------------------------------------------------------------------
__global__ void k_deg_init(int n) {
    int i = blockIdx.x * blockDim.x + threadIdx.x;
    if (i < n) g_deg[i] = 1;
}

__global__ void k_deg_count(const void* ei, int e) {
    int i = blockIdx.x * blockDim.x + threadIdx.x;
    if (i < e) {
        int d = edge_at(ei, e, 1, i);
        atomicAdd(&g_deg[d], 1);
    }
}

__global__ void k_dinv(int n) {
    int i = blockIdx.x * blockDim.x + threadIdx.x;
    if (i < n) g_dinv[i] = rsqrtf((float)g_deg[i]);
}

// ---------------------------------------------------------------------------
// GEMM: out-tile = X[rows0:rows0+32, :CIN] @ W[CIN, COUT]
//   L==1 : X = x input,   writes g_xw1   and g_agg1 = dinv^2 * xw1
//   L==2 : X = g_agg1 with fused (+b1, relu), writes g_xw2 and
//          out = b2 + dinv^2 * xw2   (self-loop + bias init for scatter2)
// blockDim == COUT (one column per thread), 32 rows per block.
// ---------------------------------------------------------------------------
template <int CIN, int COUT, int L>
__global__ void __launch_bounds__(COUT)
k_gemm(const float* __restrict__ X, const float* __restrict__ W,
       const float* __restrict__ bin, const float* __restrict__ bout,
       float* __restrict__ extout, int n)
{
    constexpr int ROWS = 32;
    __shared__ float xs[ROWS * CIN];

    const int row0 = blockIdx.x * ROWS;
    const int tid  = threadIdx.x;
    const int nr   = min(ROWS, n - row0);

    // cooperative load of the row tile (coalesced, conflict-free row-major)
    for (int idx = tid; idx < nr * CIN; idx += COUT) {
        int r = idx / CIN;
        int k = idx - r * CIN;
        float v;
        if (L == 1) {
            v = X[(size_t)(row0 + r) * CIN + k];
        } else {
            v = g_agg1[(size_t)(row0 + r) * CIN + k];
            v = fmaxf(v + bin[k], 0.0f);            // fused +b1, relu
        }
        xs[idx] = v;
    }
    __syncthreads();

    float acc[ROWS];
#pragma unroll
    for (int r = 0; r < ROWS; r++) acc[r] = 0.0f;

    const int col = tid;
#pragma unroll 4
    for (int k = 0; k < CIN; k++) {
        float wk = W[k * COUT + col];               // coalesced across warp
#pragma unroll
        for (int r = 0; r < ROWS; r++)
            acc[r] += xs[r * CIN + k] * wk;         // warp-broadcast LDS
    }

    for (int r = 0; r < nr; r++) {
        size_t o  = (size_t)(row0 + r) * COUT + col;
        float  v  = acc[r];
        float  di = g_dinv[row0 + r];
        if (L == 1) {
            g_xw1[o]  = v;
            g_agg1[o] = di * di * v;                // self-loop contribution
        } else {
            g_xw2[o]  = v;
            extout[o] = bout[col] + di * di * v;    // self-loop + b2
        }
    }
}

// ---------------------------------------------------------------------------
// Scatter: for each edge (s,d): AGG[d, :] += dinv[s]*dinv[d] * XW[s, :]
// C/4 threads per edge, float4 gather + vector RED (no return value).
// ---------------------------------------------------------------------------
__device__ __forceinline__ void red_add_f32x4(float* p, float4 v) {
    asm volatile("red.global.add.v4.f32 [%0], {%1, %2, %3, %4};"
                 :: "l"(p), "f"(v.x), "f"(v.y), "f"(v.z), "f"(v.w)
                 : "memory");
}

template <int C, int L>
__global__ void k_scatter(const void* __restrict__ ei,
                          float* __restrict__ extout, int e)
{
    constexpr int G = C / 4;                        // threads per edge
    int t    = blockIdx.x * blockDim.x + threadIdx.x;
    int gid  = t / G;
    int lane = t - gid * G;
    if (gid >= e) return;

    int s = edge_at(ei, e, 0, gid);
    int d = edge_at(ei, e, 1, gid);
    float w = g_dinv[s] * g_dinv[d];

    const float* xw  = (L == 1) ? g_xw1  : g_xw2;
    float*       agg = (L == 1) ? g_agg1 : extout;

    float4 v = *(const float4*)(xw + (size_t)s * C + lane * 4);
    v.x *= w; v.y *= w; v.z *= w; v.w *= w;
    red_add_f32x4(agg + (size_t)d * C + lane * 4, v);
}

// ---------------------------------------------------------------------------
// Launch
// ---------------------------------------------------------------------------
extern "C" void kernel_launch(void* const* d_in, const int* in_sizes, int n_in,
                              void* d_out, int out_size)
{
    const float* x  = (const float*)d_in[0];
    const void*  ei = d_in[1];
    const float* W1 = (const float*)d_in[2];
    const float* b1 = (const float*)d_in[3];
    const float* W2 = (const float*)d_in[4];
    const float* b2 = (const float*)d_in[5];
    float*       out = (float*)d_out;

    const int n = in_sizes[0] / IN_C;     // 100000
    const int e = in_sizes[1] / 2;        // 1600000

    const int TB = 256;

    k_detect<<<1, 1>>>((const int*)ei);
    k_deg_init <<<(n + TB - 1) / TB, TB>>>(n);
    k_deg_count<<<(e + TB - 1) / TB, TB>>>(ei, e);
    k_dinv     <<<(n + TB - 1) / TB, TB>>>(n);

    // Layer 1
    k_gemm<IN_C, HID_C, 1><<<(n + 31) / 32, HID_C>>>(x, W1, nullptr, nullptr,
                                                     nullptr, n);
    {
        long long threads = (long long)e * (HID_C / 4);
        int grid = (int)((threads + TB - 1) / TB);
        k_scatter<HID_C, 1><<<grid, TB>>>(ei, nullptr, e);
    }

    // Layer 2 (fused relu+b1 on input; out initialized with b2 + self-loop)
    k_gemm<HID_C, OUT_C, 2><<<(n + 31) / 32, OUT_C>>>(nullptr, W2, b1, b2,
                                                      out, n);
    {
        long long threads = (long long)e * (OUT_C / 4);
        int grid = (int)((threads + TB - 1) / TB);
        k_scatter<OUT_C, 2><<<grid, TB>>>(ei, out, e);
    }
}

// round 3
// speedup vs baseline: 1.1948x; 1.1948x over previous
#include <cuda_runtime.h>
#include <stdint.h>

#define NMAX   100000
#define EMAX   1600000
#define IN_C   128
#define HID_C  128
#define OUT_C  64
#define SCAN_T 1024

// ---------------------------------------------------------------------------
// Scratch (__device__ globals). Keep total well under ~120 MiB: lazy module
// load materializes these during the harness's correctness run and counts
// against its device-memory delta guard.
//   g_xws : layer-1 holds dinv-scaled x@W1 (100k x 128); reused afterwards as
//           dinv-scaled h@W2 (100k x 64).
//   g_agg1: layer-1 conv output (input to GEMM2).
// Total: 51.2 + 51.2 + 6.4 + ~1.6 MB  ~= 105 MiB.
// ---------------------------------------------------------------------------
__device__ float g_xws [(size_t)NMAX * HID_C];
__device__ float g_agg1[(size_t)NMAX * HID_C];
__device__ float g_dinv[NMAX];
__device__ int   g_deg [NMAX];                   // in-degree (edges only)
__device__ int   g_csr_off[NMAX];                // CSR segment start
__device__ int   g_cursor [NMAX];                // build cursor
__device__ int   g_csr_src[EMAX];                // src ids bucketed by dst
__device__ int   g_is64;

// ---------------------------------------------------------------------------
// Edge accessor: edge_index may be int64 or int32 depending on jax x64 config
// ---------------------------------------------------------------------------
__device__ __forceinline__ int edge_at(const void* ei, int etot, int which, int idx) {
    if (g_is64)
        return (int)((const long long*)ei)[(size_t)which * etot + idx];
    else
        return ((const int*)ei)[(size_t)which * etot + idx];
}

__global__ void k_detect(const int* ei32) {
    int ok64 = 1;
#pragma unroll
    for (int i = 0; i < 16; i++)
        if (ei32[2 * i + 1] != 0) ok64 = 0;
    g_is64 = ok64;
}

// ---------------------------------------------------------------------------
// Degree / normalization
// ---------------------------------------------------------------------------
__global__ void k_deg_zero(int n) {
    int i = blockIdx.x * blockDim.x + threadIdx.x;
    if (i < n) g_deg[i] = 0;
}

__global__ void k_deg_count(const void* ei, int e) {
    int i = blockIdx.x * blockDim.x + threadIdx.x;
    if (i < e) atomicAdd(&g_deg[edge_at(ei, e, 1, i)], 1);
}

__global__ void k_dinv(int n) {
    int i = blockIdx.x * blockDim.x + threadIdx.x;
    if (i < n) g_dinv[i] = rsqrtf((float)(g_deg[i] + 1));   // +1 self-loop
}

// Single-block exclusive scan of g_deg -> g_csr_off (also seeds g_cursor)
__global__ void __launch_bounds__(SCAN_T) k_scan(int n) {
    __shared__ int ssum[SCAN_T];
    int tid   = threadIdx.x;
    int chunk = (n + SCAN_T - 1) / SCAN_T;
    int b = tid * chunk, e2 = min(b + chunk, n);
    int s = 0;
    for (int i = b; i < e2; i++) s += g_deg[i];
    ssum[tid] = s;
    __syncthreads();
    for (int d = 1; d < SCAN_T; d <<= 1) {
        int v = (tid >= d) ? ssum[tid - d] : 0;
        __syncthreads();
        ssum[tid] += v;
        __syncthreads();
    }
    int off = (tid == 0) ? 0 : ssum[tid - 1];
    for (int i = b; i < e2; i++) {
        g_csr_off[i] = off;
        g_cursor[i]  = off;
        off += g_deg[i];
    }
}

__global__ void k_csr_build(const void* ei, int e) {
    int i = blockIdx.x * blockDim.x + threadIdx.x;
    if (i < e) {
        int s = edge_at(ei, e, 0, i);
        int d = edge_at(ei, e, 1, i);
        int slot = atomicAdd(&g_cursor[d], 1);
        g_csr_src[slot] = s;
    }
}

// ---------------------------------------------------------------------------
// GEMM: 32-row x COUT tile per block, one column per thread.
//   L==1 : X = input x                    -> g_xws = dinv * (x @ W1)
//   L==2 : X = relu(g_agg1 + b1) (fused)  -> g_xws = dinv * (h @ W2)
// Epilogue pre-scales by dinv[row] so aggregation needs no per-source dinv.
// ---------------------------------------------------------------------------
template <int CIN, int COUT, int L>
__global__ void __launch_bounds__(COUT)
k_gemm(const float* __restrict__ X, const float* __restrict__ W,
       const float* __restrict__ bin, int n)
{
    constexpr int ROWS = 32;
    __shared__ float xs[ROWS * CIN];

    const int row0 = blockIdx.x * ROWS;
    const int tid  = threadIdx.x;
    const int nr   = min(ROWS, n - row0);

    for (int idx = tid; idx < nr * CIN; idx += COUT) {
        int r = idx / CIN;
        int k = idx - r * CIN;
        float v;
        if (L == 1) {
            v = X[(size_t)(row0 + r) * CIN + k];
        } else {
            v = g_agg1[(size_t)(row0 + r) * CIN + k];
            v = fmaxf(v + bin[k], 0.0f);
        }
        xs[idx] = v;
    }
    __syncthreads();

    float acc[ROWS];
#pragma unroll
    for (int r = 0; r < ROWS; r++) acc[r] = 0.0f;

    const int col = tid;
    for (int k = 0; k < CIN; k += 4) {
        float w0 = W[(k + 0) * COUT + col];
        float w1 = W[(k + 1) * COUT + col];
        float w2 = W[(k + 2) * COUT + col];
        float w3 = W[(k + 3) * COUT + col];
#pragma unroll
        for (int r = 0; r < ROWS; r++) {
            float4 xv = *(const float4*)&xs[r * CIN + k];   // warp-broadcast LDS.128
            acc[r] = fmaf(xv.x, w0,
                     fmaf(xv.y, w1,
                     fmaf(xv.z, w2,
                     fmaf(xv.w, w3, acc[r]))));
        }
    }

    for (int r = 0; r < nr; r++)
        g_xws[(size_t)(row0 + r) * COUT + col] = g_dinv[row0 + r] * acc[r];
}

// ---------------------------------------------------------------------------
// Pull aggregation: node per (block, threadIdx.y), channel per threadIdx.x.
//   out[d,c] = dinv[d] * ( sum_{s in CSR[d]} xws[s,c] + xws[d,c] )
//   L==2 additionally adds b2 and writes to extout.
// ---------------------------------------------------------------------------
template <int C, int L>
__global__ void k_agg(float* __restrict__ extout, const float* __restrict__ b2,
                      int n)
{
    int node = blockIdx.x * blockDim.y + threadIdx.y;
    if (node >= n) return;
    int tid = threadIdx.x;

    const float* __restrict__ xw = g_xws;

    int beg = g_csr_off[node];
    int end = beg + g_deg[node];
    float acc = xw[(size_t)node * C + tid];         // self-loop term

    int j = beg;
    for (; j + 4 <= end; j += 4) {                  // 4-way MLP
        int s0 = g_csr_src[j + 0];
        int s1 = g_csr_src[j + 1];
        int s2 = g_csr_src[j + 2];
        int s3 = g_csr_src[j + 3];
        float v0 = xw[(size_t)s0 * C + tid];
        float v1 = xw[(size_t)s1 * C + tid];
        float v2 = xw[(size_t)s2 * C + tid];
        float v3 = xw[(size_t)s3 * C + tid];
        acc += v0; acc += v1; acc += v2; acc += v3;
    }
    for (; j < end; ++j)
        acc += xw[(size_t)g_csr_src[j] * C + tid];

    float r = g_dinv[node] * acc;

    if (L == 1)
        g_agg1[(size_t)node * C + tid] = r;
    else
        extout[(size_t)node * C + tid] = b2[tid] + r;
}

// ---------------------------------------------------------------------------
// Launch
// ---------------------------------------------------------------------------
extern "C" void kernel_launch(void* const* d_in, const int* in_sizes, int n_in,
                              void* d_out, int out_size)
{
    const float* x  = (const float*)d_in[0];
    const void*  ei = d_in[1];
    const float* W1 = (const float*)d_in[2];
    const float* b1 = (const float*)d_in[3];
    const float* W2 = (const float*)d_in[4];
    const float* b2 = (const float*)d_in[5];
    float*       out = (float*)d_out;

    const int n = in_sizes[0] / IN_C;     // 100000
    const int e = in_sizes[1] / 2;        // 1600000
    const int TB = 256;

    k_detect   <<<1, 1>>>((const int*)ei);
    k_deg_zero <<<(n + TB - 1) / TB, TB>>>(n);
    k_deg_count<<<(e + TB - 1) / TB, TB>>>(ei, e);
    k_scan     <<<1, SCAN_T>>>(n);
    k_dinv     <<<(n + TB - 1) / TB, TB>>>(n);
    k_csr_build<<<(e + TB - 1) / TB, TB>>>(ei, e);

    // Layer 1: xws = dinv * (x @ W1); agg1 = dinv * (sum + self)
    k_gemm<IN_C, HID_C, 1><<<(n + 31) / 32, HID_C>>>(x, W1, nullptr, n);
    {
        dim3 blk(HID_C, 1);
        k_agg<HID_C, 1><<<n, blk>>>(nullptr, nullptr, n);
    }

    // Layer 2: xws = dinv * (relu(agg1+b1) @ W2); out = b2 + dinv*(sum+self)
    k_gemm<HID_C, OUT_C, 2><<<(n + 31) / 32, OUT_C>>>(nullptr, W2, b1, n);
    {
        dim3 blk(OUT_C, 2);
        k_agg<OUT_C, 2><<<(n + 1) / 2, blk>>>(out, b2, n);
    }
}

// round 4
// speedup vs baseline: 2.2478x; 1.8813x over previous
#include <cuda_runtime.h>
#include <stdint.h>

#define NMAX   100000
#define EMAX   1600000
#define IN_C   128
#define HID_C  128
#define OUT_C  64

#define SCAN_B 256                       // elems per scan block
#define NBLK   ((NMAX + SCAN_B - 1) / SCAN_B)   // 391

// ---------------------------------------------------------------------------
// Scratch (__device__ globals; total ~105 MiB, safely under the alloc guard)
// ---------------------------------------------------------------------------
__device__ float g_xws [(size_t)NMAX * HID_C];   // dinv-scaled X@W (reused L2)
__device__ float g_agg1[(size_t)NMAX * HID_C];   // layer-1 conv output
__device__ float g_dinv[NMAX];
__device__ int   g_deg [NMAX];                   // in-degree (edges only)
__device__ int   g_csr_off[NMAX];
__device__ int   g_cursor [NMAX];
__device__ int   g_csr_src[EMAX];
__device__ int   g_bsum[NBLK + 1];               // per-block sums / offsets
__device__ int   g_is64;

// ---------------------------------------------------------------------------
// Edge accessor (int64 vs int32 depending on jax x64 config)
// ---------------------------------------------------------------------------
__device__ __forceinline__ int edge_at(const void* ei, int etot, int which, int idx) {
    if (g_is64)
        return (int)((const long long*)ei)[(size_t)which * etot + idx];
    else
        return ((const int*)ei)[(size_t)which * etot + idx];
}

__global__ void k_detect(const int* ei32) {
    int ok64 = 1;
#pragma unroll
    for (int i = 0; i < 16; i++)
        if (ei32[2 * i + 1] != 0) ok64 = 0;
    g_is64 = ok64;
}

// ---------------------------------------------------------------------------
// Degree / normalization
// ---------------------------------------------------------------------------
__global__ void k_deg_zero(int n) {
    int i = blockIdx.x * blockDim.x + threadIdx.x;
    if (i < n) g_deg[i] = 0;
}

__global__ void k_deg_count(const void* ei, int e) {
    int i = blockIdx.x * blockDim.x + threadIdx.x;
    if (i < e) atomicAdd(&g_deg[edge_at(ei, e, 1, i)], 1);
}

__global__ void k_dinv(int n) {
    int i = blockIdx.x * blockDim.x + threadIdx.x;
    if (i < n) g_dinv[i] = rsqrtf((float)(g_deg[i] + 1));   // +1 self-loop
}

// ---------------------------------------------------------------------------
// 3-phase parallel exclusive scan of g_deg -> g_csr_off / g_cursor
// ---------------------------------------------------------------------------
__global__ void __launch_bounds__(SCAN_B) k_scanA(int n) {   // block reduce
    __shared__ int sh[SCAN_B / 32];
    int i = blockIdx.x * SCAN_B + threadIdx.x;
    int v = (i < n) ? g_deg[i] : 0;
#pragma unroll
    for (int o = 16; o > 0; o >>= 1) v += __shfl_down_sync(0xffffffffu, v, o);
    if ((threadIdx.x & 31) == 0) sh[threadIdx.x >> 5] = v;
    __syncthreads();
    if (threadIdx.x < SCAN_B / 32) {
        int w = sh[threadIdx.x];
#pragma unroll
        for (int o = SCAN_B / 64; o > 0; o >>= 1)
            w += __shfl_down_sync(0xffffffffu, w, o, SCAN_B / 32);
        if (threadIdx.x == 0) g_bsum[blockIdx.x] = w;
    }
}

__global__ void __launch_bounds__(512) k_scanB(int nblk) {   // scan block sums
    __shared__ int sh[512];
    int tid = threadIdx.x;
    int v = (tid < nblk) ? g_bsum[tid] : 0;
    sh[tid] = v;
    __syncthreads();
    for (int d = 1; d < 512; d <<= 1) {
        int t = (tid >= d) ? sh[tid - d] : 0;
        __syncthreads();
        sh[tid] += t;
        __syncthreads();
    }
    if (tid < nblk) g_bsum[tid] = sh[tid] - v;               // exclusive
}

__global__ void __launch_bounds__(SCAN_B) k_scanC(int n) {   // local scan + off
    __shared__ int sh[SCAN_B];
    int i   = blockIdx.x * SCAN_B + threadIdx.x;
    int tid = threadIdx.x;
    int v = (i < n) ? g_deg[i] : 0;
    sh[tid] = v;
    __syncthreads();
    for (int d = 1; d < SCAN_B; d <<= 1) {
        int t = (tid >= d) ? sh[tid - d] : 0;
        __syncthreads();
        sh[tid] += t;
        __syncthreads();
    }
    if (i < n) {
        int off = g_bsum[blockIdx.x] + sh[tid] - v;          // exclusive
        g_csr_off[i] = off;
        g_cursor[i]  = off;
    }
}

__global__ void k_csr_build(const void* ei, int e) {
    int i = blockIdx.x * blockDim.x + threadIdx.x;
    if (i < e) {
        int s = edge_at(ei, e, 0, i);
        int d = edge_at(ei, e, 1, i);
        int slot = atomicAdd(&g_cursor[d], 1);
        g_csr_src[slot] = s;
    }
}

// ---------------------------------------------------------------------------
// GEMM: 32-row x COUT tile per block, one column per thread.
//   L==1 : X = input x                    -> g_xws = dinv * (x @ W1)
//   L==2 : X = relu(g_agg1 + b1) (fused)  -> g_xws = dinv * (h @ W2)
// ---------------------------------------------------------------------------
template <int CIN, int COUT, int L>
__global__ void __launch_bounds__(COUT)
k_gemm(const float* __restrict__ X, const float* __restrict__ W,
       const float* __restrict__ bin, int n)
{
    constexpr int ROWS = 32;
    __shared__ float xs[ROWS * CIN];

    const int row0 = blockIdx.x * ROWS;
    const int tid  = threadIdx.x;
    const int nr   = min(ROWS, n - row0);

    for (int idx = tid; idx < nr * CIN; idx += COUT) {
        int r = idx / CIN;
        int k = idx - r * CIN;
        float v;
        if (L == 1) {
            v = X[(size_t)(row0 + r) * CIN + k];
        } else {
            v = g_agg1[(size_t)(row0 + r) * CIN + k];
            v = fmaxf(v + bin[k], 0.0f);
        }
        xs[idx] = v;
    }
    __syncthreads();

    float acc[ROWS];
#pragma unroll
    for (int r = 0; r < ROWS; r++) acc[r] = 0.0f;

    const int col = tid;
    for (int k = 0; k < CIN; k += 4) {
        float w0 = W[(k + 0) * COUT + col];
        float w1 = W[(k + 1) * COUT + col];
        float w2 = W[(k + 2) * COUT + col];
        float w3 = W[(k + 3) * COUT + col];
#pragma unroll
        for (int r = 0; r < ROWS; r++) {
            float4 xv = *(const float4*)&xs[r * CIN + k];
            acc[r] = fmaf(xv.x, w0,
                     fmaf(xv.y, w1,
                     fmaf(xv.z, w2,
                     fmaf(xv.w, w3, acc[r]))));
        }
    }

    for (int r = 0; r < nr; r++)
        g_xws[(size_t)(row0 + r) * COUT + col] = g_dinv[row0 + r] * acc[r];
}

// ---------------------------------------------------------------------------
// Pull aggregation (vectorized): C/4 lanes per node, float4 per lane.
//   out[d, 4c:4c+4] = dinv[d] * ( sum_{s in CSR[d]} xws[s] + xws[d] ) (+b2)
// ---------------------------------------------------------------------------
template <int C, int L>
__global__ void k_agg(float* __restrict__ extout, const float* __restrict__ b2,
                      int n)
{
    constexpr int LANES = C / 4;
    int node = blockIdx.x * blockDim.y + threadIdx.y;
    if (node >= n) return;
    int lane = threadIdx.x;

    const float4* __restrict__ xw = (const float4*)g_xws;

    int beg = g_csr_off[node];
    int end = beg + g_deg[node];

    float4 a = xw[(size_t)node * LANES + lane];     // self-loop term
    float ax = a.x, ay = a.y, az = a.z, aw = a.w;

    int j = beg;
    for (; j + 4 <= end; j += 4) {
        int s0 = g_csr_src[j + 0];
        int s1 = g_csr_src[j + 1];
        int s2 = g_csr_src[j + 2];
        int s3 = g_csr_src[j + 3];
        float4 v0 = xw[(size_t)s0 * LANES + lane];
        float4 v1 = xw[(size_t)s1 * LANES + lane];
        float4 v2 = xw[(size_t)s2 * LANES + lane];
        float4 v3 = xw[(size_t)s3 * LANES + lane];
        ax += v0.x + v1.x + v2.x + v3.x;
        ay += v0.y + v1.y + v2.y + v3.y;
        az += v0.z + v1.z + v2.z + v3.z;
        aw += v0.w + v1.w + v2.w + v3.w;
    }
    for (; j < end; ++j) {
        float4 v = xw[(size_t)g_csr_src[j] * LANES + lane];
        ax += v.x; ay += v.y; az += v.z; aw += v.w;
    }

    float di = g_dinv[node];
    float4 r;
    r.x = di * ax; r.y = di * ay; r.z = di * az; r.w = di * aw;

    if (L == 1) {
        ((float4*)g_agg1)[(size_t)node * LANES + lane] = r;
    } else {
        const float4 bb = ((const float4*)b2)[lane];
        r.x += bb.x; r.y += bb.y; r.z += bb.z; r.w += bb.w;
        ((float4*)extout)[(size_t)node * LANES + lane] = r;
    }
}

// ---------------------------------------------------------------------------
// Launch
// ---------------------------------------------------------------------------
extern "C" void kernel_launch(void* const* d_in, const int* in_sizes, int n_in,
                              void* d_out, int out_size)
{
    const float* x  = (const float*)d_in[0];
    const void*  ei = d_in[1];
    const float* W1 = (const float*)d_in[2];
    const float* b1 = (const float*)d_in[3];
    const float* W2 = (const float*)d_in[4];
    const float* b2 = (const float*)d_in[5];
    float*       out = (float*)d_out;

    const int n = in_sizes[0] / IN_C;     // 100000
    const int e = in_sizes[1] / 2;        // 1600000
    const int TB = 256;
    const int nblk = (n + SCAN_B - 1) / SCAN_B;

    k_detect   <<<1, 1>>>((const int*)ei);
    k_deg_zero <<<(n + TB - 1) / TB, TB>>>(n);
    k_deg_count<<<(e + TB - 1) / TB, TB>>>(ei, e);
    k_scanA    <<<nblk, SCAN_B>>>(n);
    k_scanB    <<<1, 512>>>(nblk);
    k_scanC    <<<nblk, SCAN_B>>>(n);
    k_dinv     <<<(n + TB - 1) / TB, TB>>>(n);
    k_csr_build<<<(e + TB - 1) / TB, TB>>>(ei, e);

    // Layer 1
    k_gemm<IN_C, HID_C, 1><<<(n + 31) / 32, HID_C>>>(x, W1, nullptr, n);
    {
        dim3 blk(HID_C / 4, 8);           // 32 lanes x 8 nodes = 256 thr
        k_agg<HID_C, 1><<<(n + 7) / 8, blk>>>(nullptr, nullptr, n);
    }

    // Layer 2
    k_gemm<HID_C, OUT_C, 2><<<(n + 31) / 32, OUT_C>>>(nullptr, W2, b1, n);
    {
        dim3 blk(OUT_C / 4, 16);          // 16 lanes x 16 nodes = 256 thr
        k_agg<OUT_C, 2><<<(n + 15) / 16, blk>>>(out, b2, n);
    }
}